// round 5
// baseline (speedup 1.0000x reference)
#include <cuda_runtime.h>
#include <cstdint>
#include <math.h>

// ============================================================================
// ProbSparse attention: B=4,H=8,T=12,N=325,D=64, FACTOR=5 -> U=30
// out[b,n,t,h*64+d] = ctx[b,h,t,n,d]
// K and V both resident in SMEM; scores/softmax/GEMV fused per warp.
// Phase 2 uses 8-lane subgroups per query -> conflict-free row gathers.
// ============================================================================

#define Bc 4
#define Hc 8
#define Tc 12
#define Nc 325
#define Dc 64
#define Uc 30
#define Gc (Bc*Hc*Tc)      // 384 groups
#define NT 480             // threads per block (15 warps)
#define NW 15
#define KVS 68             // padded row stride (floats)
#define NSTEP 11           // ceil(325/32)
#define NPASS 6            // ceil(325/60) query passes in phase 2

// ---------------- shared memory layout (float offsets) ----------------
#define OFF_K    0                         // 325*68 = 22100
#define OFF_V    (Nc*KVS)                  // 22100 -> 44200
#define OFF_M    (OFF_V + Nc*KVS)          // 328
#define OFF_Q    (OFF_M + 328)             // 30*64
#define OFF_UPD  (OFF_Q + Uc*Dc)           // 30*64
#define OFF_MEAN (OFF_UPD + Uc*Dc)         // 64
#define OFF_RED  (OFF_MEAN + 64)           // 1024 (15 warps x 64 partials)
#define OFF_SEL  (OFF_RED + 1024)          // 32 ints
#define OFF_RANK (OFF_SEL + 32)            // 325 ints (+pad)
#define SMEM_FLOATS (OFF_RANK + Nc + 3)
#define SMEM_BYTES (SMEM_FLOATS * 4)       // ~199.3 KB

__device__ int g_idx[Nc * Uc];

// ---------------- threefry2x32 (exact JAX schedule) ----------------
__device__ __forceinline__ uint32_t rotl32(uint32_t x, int r) {
    return (x << r) | (x >> (32 - r));
}

__device__ __forceinline__ void tf2x32(uint32_t k0, uint32_t k1,
                                       uint32_t x0, uint32_t x1,
                                       uint32_t& o0, uint32_t& o1) {
    uint32_t ks2 = k0 ^ k1 ^ 0x1BD11BDAu;
    x0 += k0; x1 += k1;
#define TF_R(r) { x0 += x1; x1 = rotl32(x1, r); x1 ^= x0; }
    TF_R(13) TF_R(15) TF_R(26) TF_R(6)   x0 += k1;  x1 += ks2 + 1u;
    TF_R(17) TF_R(29) TF_R(16) TF_R(24)  x0 += ks2; x1 += k0  + 2u;
    TF_R(13) TF_R(15) TF_R(26) TF_R(6)   x0 += k0;  x1 += k1  + 3u;
    TF_R(17) TF_R(29) TF_R(16) TF_R(24)  x0 += k1;  x1 += ks2 + 4u;
    TF_R(13) TF_R(15) TF_R(26) TF_R(6)   x0 += ks2; x1 += k0  + 5u;
#undef TF_R
    o0 = x0; o1 = x1;
}

// idx_sample = jax.random.randint(key(42), (325,30), 0, 325)  [verified bit-exact]
__global__ void idx_kernel() {
    int j = blockIdx.x * blockDim.x + threadIdx.x;
    if (j >= Nc * Uc) return;
    const uint32_t SPAN = 325u;
    const uint32_t MULT = 321u;  // (2^32) mod 325
    uint32_t a0, a1, b0, b1;
    tf2x32(0u, 42u, 0u, 0u, a0, a1);
    tf2x32(0u, 42u, 0u, 1u, b0, b1);
    uint32_t h0, h1, l0, l1;
    tf2x32(a0, a1, 0u, (uint32_t)j, h0, h1);
    uint32_t hi = h0 ^ h1;
    tf2x32(b0, b1, 0u, (uint32_t)j, l0, l1);
    uint32_t lo = l0 ^ l1;
    g_idx[j] = (int)(((hi % SPAN) * MULT + (lo % SPAN)) % SPAN);
}

__device__ __forceinline__ float dot4(float4 a, float4 b) {
    return a.x * b.x + a.y * b.y + a.z * b.z + a.w * b.w;
}

__device__ __forceinline__ void cp_async16(uint32_t dst, const void* src) {
    asm volatile("cp.async.cg.shared.global [%0], [%1], 16;\n"
                 :: "r"(dst), "l"(src));
}

// ---------------- main fused kernel: one block per (b,h,t) group ----------------
__global__ __launch_bounds__(NT, 1)
void probsparse_kernel(const float* __restrict__ Q,
                       const float* __restrict__ K,
                       const float* __restrict__ V,
                       float* __restrict__ out) {
    extern __shared__ float sm[];
    float* sK    = sm + OFF_K;
    float* sV    = sm + OFF_V;
    float* sM    = sm + OFF_M;
    float* sQ    = sm + OFF_Q;
    float* sUpd  = sm + OFF_UPD;
    float* sMean = sm + OFF_MEAN;
    float* sRed  = sm + OFF_RED;
    int*   sSel  = (int*)(sm + OFF_SEL);
    int*   sRank = (int*)(sm + OFF_RANK);

    const int g    = blockIdx.x;
    const int tid  = threadIdx.x;
    const int lane = tid & 31;
    const int warp = tid >> 5;
    const size_t base = (size_t)g * Nc * Dc;

    // ---- phase 1: stage K AND V into SMEM via cp.async; init rank ----
    {
        uint32_t sb = (uint32_t)__cvta_generic_to_shared(sm);
        const float4* K4 = (const float4*)(K + base);
        const float4* V4 = (const float4*)(V + base);
        for (int i = tid; i < Nc * Dc / 4; i += NT) {
            int n = i >> 4, d4 = i & 15;
            uint32_t off = (uint32_t)(n * KVS + d4 * 4) * 4u;
            cp_async16(sb + (OFF_K * 4u) + off, K4 + i);
            cp_async16(sb + (OFF_V * 4u) + off, V4 + i);
        }
        asm volatile("cp.async.commit_group;\n");
        for (int i = tid; i < Nc; i += NT) sRank[i] = -1;
        asm volatile("cp.async.wait_group 0;\n" ::: "memory");
    }
    __syncthreads();

    // ========================================================================
    // phase 2: sparsity measure M[n] = max_u(qk) - mean_u(qk).
    // 8-lane subgroup per query: each sample's K row is read as one
    // conflict-free 128B phase (8 lanes x 16B consecutive). Dot finished by
    // 3 shfl_xor. 4 queries per warp, 60 per pass, 6 passes.
    // ========================================================================
    {
        const int sub = lane >> 3;     // query slot 0..3 within warp
        const int sl  = lane & 7;      // lane within subgroup
#pragma unroll 1
        for (int p = 0; p < NPASS; p++) {
            int n = p * 60 + warp * 4 + sub;
            bool act = n < Nc;
            int nn = act ? n : Nc - 1;
            const float4* qr = (const float4*)(Q + base + (size_t)nn * Dc + sl * 8);
            float4 qA = qr[0], qB = qr[1];
            const int* idxp = g_idx + nn * Uc;
            float mx = -INFINITY, sum = 0.f;
            int kn0 = idxp[0], kn1 = idxp[1];
#pragma unroll
            for (int u = 0; u < Uc; u += 2) {
                int knA = kn0, knB = kn1;
                if (u + 2 < Uc) { kn0 = idxp[u + 2]; kn1 = idxp[u + 3]; }
                const float4* krA = (const float4*)&sK[knA * KVS + sl * 8];
                const float4* krB = (const float4*)&sK[knB * KVS + sl * 8];
                float4 kA0 = krA[0], kA1 = krA[1];
                float4 kB0 = krB[0], kB1 = krB[1];
                float pa = dot4(qA, kA0) + dot4(qB, kA1);
                float pb = dot4(qA, kB0) + dot4(qB, kB1);
                pa += __shfl_xor_sync(0xffffffffu, pa, 1);
                pb += __shfl_xor_sync(0xffffffffu, pb, 1);
                pa += __shfl_xor_sync(0xffffffffu, pa, 2);
                pb += __shfl_xor_sync(0xffffffffu, pb, 2);
                pa += __shfl_xor_sync(0xffffffffu, pa, 4);
                pb += __shfl_xor_sync(0xffffffffu, pb, 4);
                mx = fmaxf(mx, fmaxf(pa, pb));
                sum += pa + pb;
            }
            if (act && sl == 0) sM[n] = mx - sum * (1.0f / Uc);
        }
    }
    __syncthreads();

    // ---- phase 3: top-30 via parallel rank counting (ties -> lowest index) ----
    if (tid < Nc) {
        float mi = sM[tid];
        int rank = 0;
        for (int j = 0; j < Nc; j++) {
            float mj = sM[j];   // broadcast read
            rank += (mj > mi) || (mj == mi && j < tid) ? 1 : 0;
        }
        if (rank < Uc) { sRank[tid] = rank; sSel[rank] = tid; }
    }
    __syncthreads();

    // ---- phase 4: gather selected queries + column-mean partials of V ----
    for (int i = tid; i < Uc * Dc; i += NT) {
        int u = i >> 6, d = i & 63;
        sQ[u * Dc + d] = Q[base + (size_t)sSel[u] * Dc + d];
    }
    {   // warp w sums rows [22w, 22w+22) of V into sRed[w*64 + d]
        int n0 = warp * 22, n1 = min(Nc, n0 + 22);
        float m0 = 0.f, m1 = 0.f;
        for (int n = n0; n < n1; n++) {
            m0 += sV[n * KVS + lane];
            m1 += sV[n * KVS + lane + 32];
        }
        sRed[warp * 64 + lane]      = m0;
        sRed[warp * 64 + lane + 32] = m1;
    }
    __syncthreads();

    // ---- phase 5+8 fused (barrier-free per warp): scores -> softmax -> GEMV ----
    // warps 0-1 additionally combine the mean (reads sRed, pre-barrier data)
    if (tid < Dc) {
        float s = 0.f;
#pragma unroll
        for (int k = 0; k < NW; k++) s += sRed[k * 64 + tid];
        sMean[tid] = s * (1.0f / Nc);
    }

    {
        const int u0 = warp, u1 = warp + NW;
        const int half = lane >> 4;         // 0 or 1
        const int lsub = lane & 15;
        const int d0 = half << 5;           // 0 or 32

        float4 qa[8], qb[8];
        const float4* qa4 = (const float4*)&sQ[u0 * Dc + d0];
        const float4* qb4 = (const float4*)&sQ[u1 * Dc + d0];
#pragma unroll
        for (int j = 0; j < 8; j++) { qa[j] = qa4[j]; qb[j] = qb4[j]; }

        // --- scores: lane pairs (l, l+16) split d; each K row read once/warp ---
        float e0r[NSTEP], e1r[NSTEP];
        float lmax0 = -INFINITY, lmax1 = -INFINITY;
#pragma unroll
        for (int t = 0; t < NSTEP; t++) {
            int bn  = t * 32;
            int alo = min(bn + lsub,      Nc - 1) * KVS + d0;
            int ahi = min(bn + 16 + lsub, Nc - 1) * KVS + d0;
            const float4* klo = (const float4*)&sK[alo];
            const float4* khi = (const float4*)&sK[ahi];
            float p00 = 0.f, p01 = 0.f, p10 = 0.f, p11 = 0.f;
#pragma unroll
            for (int j = 0; j < 8; j++) {
                float4 kl = klo[j], kh = khi[j];
                p00 += dot4(qa[j], kl);
                p01 += dot4(qb[j], kl);
                p10 += dot4(qa[j], kh);
                p11 += dot4(qb[j], kh);
            }
            p00 += __shfl_xor_sync(0xffffffffu, p00, 16);
            p01 += __shfl_xor_sync(0xffffffffu, p01, 16);
            p10 += __shfl_xor_sync(0xffffffffu, p10, 16);
            p11 += __shfl_xor_sync(0xffffffffu, p11, 16);
            int n = bn + lane;
            float s0 = (half ? p10 : p00) * 0.125f;
            float s1 = (half ? p11 : p01) * 0.125f;
            bool ok = (n < Nc);
            e0r[t] = s0; e1r[t] = s1;
            lmax0 = fmaxf(lmax0, ok ? s0 : -INFINITY);
            lmax1 = fmaxf(lmax1, ok ? s1 : -INFINITY);
        }
#pragma unroll
        for (int o = 16; o > 0; o >>= 1) {
            lmax0 = fmaxf(lmax0, __shfl_xor_sync(0xffffffffu, lmax0, o));
            lmax1 = fmaxf(lmax1, __shfl_xor_sync(0xffffffffu, lmax1, o));
        }
        // --- softmax numerators in registers (e=0 beyond Nc) ---
        float lsum0 = 0.f, lsum1 = 0.f;
#pragma unroll
        for (int t = 0; t < NSTEP; t++) {
            bool ok = (t * 32 + lane) < Nc;
            float e0 = ok ? __expf(e0r[t] - lmax0) : 0.f;
            float e1 = ok ? __expf(e1r[t] - lmax1) : 0.f;
            e0r[t] = e0; e1r[t] = e1;
            lsum0 += e0; lsum1 += e1;
        }
#pragma unroll
        for (int o = 16; o > 0; o >>= 1) {
            lsum0 += __shfl_xor_sync(0xffffffffu, lsum0, o);
            lsum1 += __shfl_xor_sync(0xffffffffu, lsum1, o);
        }
        float inv0 = 1.0f / lsum0;
        float inv1 = 1.0f / lsum1;

        // --- GEMV: broadcast e via shfl, V rows conflict-free ---
        float a00 = 0.f, a01 = 0.f, a10 = 0.f, a11 = 0.f;
#pragma unroll
        for (int t = 0; t < NSTEP; t++) {
            const int cnt = (t == NSTEP - 1) ? (Nc - (NSTEP - 1) * 32) : 32;
            float e0v = e0r[t], e1v = e1r[t];
            const float* vb = &sV[t * 32 * KVS];
#pragma unroll 4
            for (int l = 0; l < cnt; l++) {
                float ee0 = __shfl_sync(0xffffffffu, e0v, l);
                float ee1 = __shfl_sync(0xffffffffu, e1v, l);
                float v0 = vb[l * KVS + lane];
                float v1 = vb[l * KVS + lane + 32];
                a00 += ee0 * v0; a01 += ee0 * v1;
                a10 += ee1 * v0; a11 += ee1 * v1;
            }
        }
        sUpd[u0 * Dc + lane]      = a00 * inv0;
        sUpd[u0 * Dc + lane + 32] = a01 * inv0;
        sUpd[u1 * Dc + lane]      = a10 * inv1;
        sUpd[u1 * Dc + lane + 32] = a11 * inv1;
    }
    __syncthreads();

    // ---- phase 9: write output (selected -> attention, else column mean) ----
    {
        const int b = g / (Hc * Tc);
        const int h = (g / Tc) % Hc;
        const int t = g % Tc;
        for (int i = tid; i < Nc * Dc / 4; i += NT) {
            int n = i >> 4, d4 = (i & 15) * 4;
            int r = sRank[n];
            float4 v = (r >= 0) ? *(float4*)&sUpd[r * Dc + d4]
                                : *(float4*)&sMean[d4];
            size_t o = ((size_t)(b * Nc + n) * Tc + t) * (size_t)(Hc * Dc)
                     + h * Dc + d4;
            *(float4*)&out[o] = v;
        }
    }
}

// ---------------- launch ----------------
extern "C" void kernel_launch(void* const* d_in, const int* in_sizes, int n_in,
                              void* d_out, int out_size) {
    const float* Q = (const float*)d_in[0];
    const float* K = (const float*)d_in[1];
    const float* V = (const float*)d_in[2];
    float* out = (float*)d_out;

    cudaFuncSetAttribute(probsparse_kernel,
                         cudaFuncAttributeMaxDynamicSharedMemorySize, SMEM_BYTES);

    idx_kernel<<<(Nc * Uc + 255) / 256, 256>>>();
    probsparse_kernel<<<Gc, NT, SMEM_BYTES>>>(Q, K, V, out);
}